// round 5
// baseline (speedup 1.0000x reference)
#include <cuda_runtime.h>
#include <math.h>

// Problem shape (fixed by the benchmark):
// video [B=8, C=1024, T=64, W=14, H=14] fp32
// params mu_x, mu_y, sigma_x, sigma_y: [N=3] fp32
// out [B, C*N] = einsum('bctwh,nwh->bcn', video, filters) / T
#define N_FILT 3
#define W_DIM 14
#define H_DIM 14
#define WH 196              // W*H
#define WH4 49              // WH/4
#define T_DIM 64
#define T_GROUPS 5          // time-slices per CTA thread-group
#define ACTIVE_THREADS (WH4 * T_GROUPS)  // 245
#define SLAB (T_DIM * WH)   // 12544 floats per (b,c)
#define SLAB4 (SLAB / 4)    // 3136 float4 per (b,c)
#define PAD_FLOATS 11264    // 44KB static smem pad -> caps occupancy at 4 CTAs/SM

// ---------------------------------------------------------------------------
// Fused kernel: one CTA per PAIR of (b,c) slabs.
//  Phase 1: compute the 3 normalized Gaussian filters (x 1/(sum+eps)/T) in smem.
//  Phase 2: each thread hoists its 3 filter float4s (position p) into registers.
//  Phase 3: dual-slab streaming loop: 2 LDG.128 + 24 FFMA per iteration.
// Static smem (~47.6KB total) caps occupancy at 4 CTAs/SM so the wave count
// (4096 / (148*4) = 6.92) has a 92%-full last wave (~1% tail idle).
// ---------------------------------------------------------------------------
__global__ __launch_bounds__(256, 4)
void fused_kernel(const float* __restrict__ video,
                  const float* __restrict__ mu_x,
                  const float* __restrict__ mu_y,
                  const float* __restrict__ sigma_x,
                  const float* __restrict__ sigma_y,
                  float* __restrict__ out,
                  int n_bc, int n_half) {
    __shared__ float pad[PAD_FLOATS];      // occupancy control (dead-guarded)
    __shared__ float fsm[N_FILT][WH];      // normalized filters
    __shared__ float red[8][2 * N_FILT];   // per-warp partials

    const int tid = threadIdx.x;
    const int wid = tid >> 5;
    const int lid = tid & 31;

    // Dead guard: n_bc is always > 0 at runtime, but the compiler cannot
    // prove it, so the pad array is kept (it controls occupancy).
    if (n_bc < 0) {
        pad[tid] = mu_x[0];
        out[tid] = pad[tid ^ 1];
    }

    // ---- Phase 1: compute filters --------------------------------------
    {
        float val[N_FILT];
        float wsum[N_FILT];
        #pragma unroll
        for (int n = 0; n < N_FILT; n++) {
            float mx = tanhf(mu_x[n]);
            float my = tanhf(mu_y[n]);
            float sgx = 1.0f / (1.0f + expf(-sigma_x[n]));
            float sgy = 1.0f / (1.0f + expf(-sigma_y[n]));
            float sx = expf(1.5f - 2.0f * sgx);
            float sy = expf(1.5f - 2.0f * sgy);
            float inv_x = 1.0f / (sx * sx + 1e-6f);
            float inv_y = 1.0f / (sy * sy + 1e-6f);
            float mux = (float)(W_DIM - 1) * ((mx + 1.0f) * 0.5f);
            float muy = (float)(H_DIM - 1) * ((my + 1.0f) * 0.5f);

            float v = 0.0f;
            if (tid < WH) {
                int w = tid / H_DIM;
                int h = tid - w * H_DIM;
                float dx = (float)w - mux;
                float dy = (float)h - muy;
                v = expf(-0.5f * (dx * dx * inv_x + dy * dy * inv_y));
            }
            val[n] = v;
            float s = v;
            #pragma unroll
            for (int off = 16; off > 0; off >>= 1)
                s += __shfl_xor_sync(0xFFFFFFFFu, s, off);
            wsum[n] = s;
        }
        if (lid == 0) {
            red[wid][0] = wsum[0];
            red[wid][1] = wsum[1];
            red[wid][2] = wsum[2];
        }
        __syncthreads();
        if (tid < WH) {
            #pragma unroll
            for (int n = 0; n < N_FILT; n++) {
                float s = 0.0f;
                #pragma unroll
                for (int w = 0; w < 8; w++) s += red[w][n];
                float scale = 1.0f / ((s + 1e-6f) * (float)T_DIM);
                fsm[n][tid] = val[n] * scale;
            }
        }
        __syncthreads();
    }

    // ---- Phase 2 + 3: dual-slab streaming -------------------------------
    const int bc0 = blockIdx.x;
    const int bc1 = blockIdx.x + n_half;
    const bool has1 = (bc1 < n_bc);

    float a0 = 0.0f, a1 = 0.0f, a2 = 0.0f;   // slab 0 accumulators
    float b0 = 0.0f, b1 = 0.0f, b2 = 0.0f;   // slab 1 accumulators

    if (tid < ACTIVE_THREADS) {
        const int g = tid / WH4;        // time-group 0..4
        const int p = tid - g * WH4;    // spatial float4 position 0..48

        const float4 f0 = ((const float4*)fsm[0])[p];
        const float4 f1 = ((const float4*)fsm[1])[p];
        const float4 f2 = ((const float4*)fsm[2])[p];

        const float4* vp0 = (const float4*)video + (size_t)bc0 * SLAB4 + p;
        const float4* vp1 = (const float4*)video + (size_t)bc1 * SLAB4 + p;

        if (has1) {
            #pragma unroll 2
            for (int t = g; t < T_DIM; t += T_GROUPS) {
                float4 u = __ldg(&vp0[t * WH4]);
                float4 v = __ldg(&vp1[t * WH4]);
                a0 += u.x * f0.x + u.y * f0.y + u.z * f0.z + u.w * f0.w;
                a1 += u.x * f1.x + u.y * f1.y + u.z * f1.z + u.w * f1.w;
                a2 += u.x * f2.x + u.y * f2.y + u.z * f2.z + u.w * f2.w;
                b0 += v.x * f0.x + v.y * f0.y + v.z * f0.z + v.w * f0.w;
                b1 += v.x * f1.x + v.y * f1.y + v.z * f1.z + v.w * f1.w;
                b2 += v.x * f2.x + v.y * f2.y + v.z * f2.z + v.w * f2.w;
            }
        } else {
            #pragma unroll 4
            for (int t = g; t < T_DIM; t += T_GROUPS) {
                float4 u = __ldg(&vp0[t * WH4]);
                a0 += u.x * f0.x + u.y * f0.y + u.z * f0.z + u.w * f0.w;
                a1 += u.x * f1.x + u.y * f1.y + u.z * f1.z + u.w * f1.w;
                a2 += u.x * f2.x + u.y * f2.y + u.z * f2.z + u.w * f2.w;
            }
        }
    }

    // warp reduction of all 6 accumulators
    #pragma unroll
    for (int off = 16; off > 0; off >>= 1) {
        a0 += __shfl_xor_sync(0xFFFFFFFFu, a0, off);
        a1 += __shfl_xor_sync(0xFFFFFFFFu, a1, off);
        a2 += __shfl_xor_sync(0xFFFFFFFFu, a2, off);
        b0 += __shfl_xor_sync(0xFFFFFFFFu, b0, off);
        b1 += __shfl_xor_sync(0xFFFFFFFFu, b1, off);
        b2 += __shfl_xor_sync(0xFFFFFFFFu, b2, off);
    }

    __syncthreads();   // red[] was read in phase 1; protect before rewrite
    if (lid == 0) {
        red[wid][0] = a0;
        red[wid][1] = a1;
        red[wid][2] = a2;
        red[wid][3] = b0;
        red[wid][4] = b1;
        red[wid][5] = b2;
    }
    __syncthreads();

    if (tid < 2 * N_FILT) {
        float s = 0.0f;
        #pragma unroll
        for (int w = 0; w < 8; w++) s += red[w][tid];
        if (tid < N_FILT) {
            out[(size_t)bc0 * N_FILT + tid] = s;
        } else if (has1) {
            out[(size_t)bc1 * N_FILT + (tid - N_FILT)] = s;
        }
    }
}

// ---------------------------------------------------------------------------
extern "C" void kernel_launch(void* const* d_in, const int* in_sizes, int n_in,
                              void* d_out, int out_size) {
    const float* video   = (const float*)d_in[0];
    const float* mu_x    = (const float*)d_in[1];
    const float* mu_y    = (const float*)d_in[2];
    const float* sigma_x = (const float*)d_in[3];
    const float* sigma_y = (const float*)d_in[4];
    float* out = (float*)d_out;

    const int n_bc = in_sizes[0] / SLAB;       // B*C = 8192
    const int n_half = (n_bc + 1) / 2;         // 4096

    fused_kernel<<<n_half, 256>>>(video, mu_x, mu_y, sigma_x, sigma_y,
                                  out, n_bc, n_half);
}

// round 6
// speedup vs baseline: 1.2160x; 1.2160x over previous
#include <cuda_runtime.h>
#include <math.h>

// Problem shape (fixed by the benchmark):
// video [B=8, C=1024, T=64, W=14, H=14] fp32
// params mu_x, mu_y, sigma_x, sigma_y: [N=3] fp32
// out [B, C*N] = einsum('bctwh,nwh->bcn', video, filters) / T
#define N_FILT 3
#define W_DIM 14
#define H_DIM 14
#define WH 196              // W*H
#define WH4 49              // WH/4
#define T_DIM 64
#define T_GROUPS 5          // time-slices per CTA thread-group
#define ACTIVE_THREADS (WH4 * T_GROUPS)  // 245
#define SLAB (T_DIM * WH)   // 12544 floats per (b,c)
#define SLAB4 (SLAB / 4)    // 3136 float4 per (b,c)

// Filters pre-scaled by 1/(sum+eps) * (1/T), stored as float4 for vector LDG.
__device__ float4 g_filt4[N_FILT * WH4];

// ---------------------------------------------------------------------------
// Pre-kernel: 3 blocks, one per filter. 224 threads (196 active). Paid once.
// ---------------------------------------------------------------------------
__global__ void filter_kernel(const float* __restrict__ mu_x,
                              const float* __restrict__ mu_y,
                              const float* __restrict__ sigma_x,
                              const float* __restrict__ sigma_y) {
    const int n = blockIdx.x;
    const int tid = threadIdx.x;
    __shared__ float red[7];

    float mx = tanhf(mu_x[n]);
    float my = tanhf(mu_y[n]);
    float sgx = 1.0f / (1.0f + expf(-sigma_x[n]));
    float sgy = 1.0f / (1.0f + expf(-sigma_y[n]));
    float sx = expf(1.5f - 2.0f * sgx);
    float sy = expf(1.5f - 2.0f * sgy);
    float inv_x = 1.0f / (sx * sx + 1e-6f);
    float inv_y = 1.0f / (sy * sy + 1e-6f);
    float mux = (float)(W_DIM - 1) * ((mx + 1.0f) * 0.5f);
    float muy = (float)(H_DIM - 1) * ((my + 1.0f) * 0.5f);

    float v = 0.0f;
    if (tid < WH) {
        int w = tid / H_DIM;
        int h = tid - w * H_DIM;
        float dx = (float)w - mux;
        float dy = (float)h - muy;
        v = expf(-0.5f * (dx * dx * inv_x + dy * dy * inv_y));
    }
    float s = v;
    #pragma unroll
    for (int off = 16; off > 0; off >>= 1)
        s += __shfl_xor_sync(0xFFFFFFFFu, s, off);
    if ((tid & 31) == 0) red[tid >> 5] = s;
    __syncthreads();
    float tot = 0.0f;
    #pragma unroll
    for (int w = 0; w < 7; w++) tot += red[w];
    float scale = 1.0f / ((tot + 1e-6f) * (float)T_DIM);
    if (tid < WH) {
        ((float*)g_filt4)[n * WH + tid] = v * scale;
    }
}

// ---------------------------------------------------------------------------
// Main kernel: one CTA per (b,c) slab. Each thread owns one spatial float4
// position p (3 filter float4s in registers) and strides time t = g, g+5, ...
// Inner loop: 1 LDG.128 + 12 FFMA. Forced to 8 CTAs/SM (32 regs): 64 warps/SM
// for max outstanding loads, and 8192/(148*8)=6.92 waves -> 92%-full tail.
// ---------------------------------------------------------------------------
__global__ __launch_bounds__(256, 8)
void pool_kernel(const float4* __restrict__ video4, float* __restrict__ out) {
    const int bc = blockIdx.x;
    const int tid = threadIdx.x;

    float a0 = 0.0f, a1 = 0.0f, a2 = 0.0f;

    if (tid < ACTIVE_THREADS) {
        const int g = tid / WH4;        // time-group 0..4
        const int p = tid - g * WH4;    // spatial float4 position 0..48

        const float4 f0 = g_filt4[p];
        const float4 f1 = g_filt4[WH4 + p];
        const float4 f2 = g_filt4[2 * WH4 + p];

        const float4* vp = video4 + bc * SLAB4 + g * WH4 + p;
        const int iters = (g == T_GROUPS - 1) ? 12 : 13;  // ceil((64-g)/5)

        #pragma unroll 2
        for (int it = 0; it < iters; it++) {
            float4 v = __ldg(vp);
            vp += T_GROUPS * WH4;
            a0 += v.x * f0.x + v.y * f0.y + v.z * f0.z + v.w * f0.w;
            a1 += v.x * f1.x + v.y * f1.y + v.z * f1.z + v.w * f1.w;
            a2 += v.x * f2.x + v.y * f2.y + v.z * f2.z + v.w * f2.w;
        }
    }

    // warp reduction (all 256 threads participate; inactive ones carry zeros)
    #pragma unroll
    for (int off = 16; off > 0; off >>= 1) {
        a0 += __shfl_xor_sync(0xFFFFFFFFu, a0, off);
        a1 += __shfl_xor_sync(0xFFFFFFFFu, a1, off);
        a2 += __shfl_xor_sync(0xFFFFFFFFu, a2, off);
    }

    __shared__ float part[8][N_FILT];
    const int wid = tid >> 5;
    const int lid = tid & 31;
    if (lid == 0) {
        part[wid][0] = a0;
        part[wid][1] = a1;
        part[wid][2] = a2;
    }
    __syncthreads();

    if (tid < N_FILT) {
        float s = 0.0f;
        #pragma unroll
        for (int w = 0; w < 8; w++) s += part[w][tid];
        out[bc * N_FILT + tid] = s;
    }
}

// ---------------------------------------------------------------------------
extern "C" void kernel_launch(void* const* d_in, const int* in_sizes, int n_in,
                              void* d_out, int out_size) {
    const float* video   = (const float*)d_in[0];
    const float* mu_x    = (const float*)d_in[1];
    const float* mu_y    = (const float*)d_in[2];
    const float* sigma_x = (const float*)d_in[3];
    const float* sigma_y = (const float*)d_in[4];
    float* out = (float*)d_out;

    const int n_bc = in_sizes[0] / SLAB;  // B*C = 8192

    filter_kernel<<<N_FILT, 224>>>(mu_x, mu_y, sigma_x, sigma_y);
    pool_kernel<<<n_bc, 256>>>((const float4*)video, out);
}